// round 16
// baseline (speedup 1.0000x reference)
#include <cuda_runtime.h>

#define T_DIM 2048
#define B_DIM 64
#define D_DIM 512

// Scratch: d[t*B + b] = 0.5 * (x[t,b,:]·Wx + bias) + 0.25 * wz
__device__ float g_d[T_DIM * B_DIM];

__device__ __forceinline__ float tanh_approx(float x) {
    float r; asm("tanh.approx.f32 %0, %1;" : "=f"(r) : "f"(x)); return r;
}
// volatile: cannot be sunk/reordered by ptxas -> prefetch actually issues early
__device__ __forceinline__ float ldg_nc(const float* p) {
    float v; asm volatile("ld.global.nc.f32 %0, [%1];" : "=f"(v) : "l"(p)); return v;
}

// Phase 1: one warp per (t,b) row. Row = 512 floats = 4 x float4 per lane.
// Stores the pre-folded tanh argument d_t = 0.5*xproj + 0.25*wz.
__global__ __launch_bounds__(256) void proj_kernel(const float* __restrict__ x,
                                                   const float* __restrict__ W,
                                                   const float* __restrict__ bias) {
    const int warp = threadIdx.x >> 5;
    const int lane = threadIdx.x & 31;
    const long long row = (long long)blockIdx.x * 8 + warp;

    const float4* __restrict__ xr = (const float4*)(x + row * D_DIM);
    const float4* __restrict__ wr = (const float4*)W;

    float acc = 0.0f;
#pragma unroll
    for (int k = 0; k < 4; k++) {
        float4 xv = xr[lane + k * 32];   // coalesced 128B/warp segments
        float4 wv = wr[lane + k * 32];   // L1/L2-resident
        acc = fmaf(xv.x, wv.x, acc);
        acc = fmaf(xv.y, wv.y, acc);
        acc = fmaf(xv.z, wv.z, acc);
        acc = fmaf(xv.w, wv.w, acc);
    }
#pragma unroll
    for (int o = 16; o; o >>= 1) acc += __shfl_xor_sync(0xffffffffu, acc, o);

    if (lane == 0) {
        float xp = acc + *bias;
        float wz = W[D_DIM];
        g_d[row] = fmaf(0.5f, xp, 0.25f * wz);
    }
}

// Phase 2: 64 independent chains (one per batch lane).
//   u_t = tanh( d_t + e * u_{t-1} ),   e = 0.25*wz,  u_0 = -1  (z_0 = 0)
//   z_t = 0.5 + 0.5*u_t   (off the recurrence chain)
// Chain/step = FFMA + MUFU.TANH ~= 21 cyc. 16-deep register prefetch via
// volatile LDG hides L2 latency under the chain.
__global__ __launch_bounds__(64) void scan_kernel(const float* __restrict__ W,
                                                  float* __restrict__ out) {
    const int b = threadIdx.x;                 // 0..63
    const float e = 0.25f * W[D_DIM];
    float u = -1.0f;

    constexpr int CH  = 16;
    constexpr int NCH = T_DIM / CH;
    float buf[2][CH];

#pragma unroll
    for (int i = 0; i < CH; i++) buf[0][i] = ldg_nc(&g_d[i * B_DIM + b]);

    for (int c = 0; c < NCH; c++) {
        const int cur = c & 1;
        if (c + 1 < NCH) {
            const float* ap = g_d + (c + 1) * CH * B_DIM + b;
#pragma unroll
            for (int i = 0; i < CH; i++) buf[cur ^ 1][i] = ldg_nc(ap + i * B_DIM);
        }
        float* __restrict__ op = out + c * CH * B_DIM + b;
#pragma unroll
        for (int i = 0; i < CH; i++) {
            float h = fmaf(u, e, buf[cur][i]);   // ~5 cyc (cross-pipe)
            u = tanh_approx(h);                  // 16 cyc MUFU.TANH
            op[i * B_DIM] = fmaf(u, 0.5f, 0.5f); // off-chain
        }
    }
}

extern "C" void kernel_launch(void* const* d_in, const int* in_sizes, int n_in,
                              void* d_out, int out_size) {
    const float* x    = (const float*)d_in[0];  // (T, B, D) f32
    const float* W    = (const float*)d_in[1];  // (D+1,)    f32
    const float* bias = (const float*)d_in[2];  // ()        f32
    float* out = (float*)d_out;                 // (T, B)    f32

    proj_kernel<<<(T_DIM * B_DIM) / 8, 256>>>(x, W, bias);
    scan_kernel<<<1, 64>>>(W, out);
}

// round 17
// speedup vs baseline: 1.0005x; 1.0005x over previous
#include <cuda_runtime.h>

#define T_DIM 2048
#define B_DIM 64
#define D_DIM 512

// Scratch: d[t*B + b] = 0.5 * (x[t,b,:]·Wx + bias) + 0.25 * wz
__device__ float g_d[T_DIM * B_DIM];

__device__ __forceinline__ float tanh_approx(float x) {
    float r; asm("tanh.approx.f32 %0, %1;" : "=f"(r) : "f"(x)); return r;
}
// volatile: cannot be sunk/reordered by ptxas -> prefetch actually issues early
__device__ __forceinline__ float ldg_nc(const float* p) {
    float v; asm volatile("ld.global.nc.f32 %0, [%1];" : "=f"(v) : "l"(p)); return v;
}

// Phase 1: one warp per (t,b) row. Row = 512 floats = 4 x float4 per lane.
// Stores the pre-folded tanh argument d_t = 0.5*xproj + 0.25*wz.
__global__ __launch_bounds__(256) void proj_kernel(const float* __restrict__ x,
                                                   const float* __restrict__ W,
                                                   const float* __restrict__ bias) {
    const int warp = threadIdx.x >> 5;
    const int lane = threadIdx.x & 31;
    const long long row = (long long)blockIdx.x * 8 + warp;

    const float4* __restrict__ xr = (const float4*)(x + row * D_DIM);
    const float4* __restrict__ wr = (const float4*)W;

    float acc = 0.0f;
#pragma unroll
    for (int k = 0; k < 4; k++) {
        float4 xv = xr[lane + k * 32];   // coalesced 128B/warp segments
        float4 wv = wr[lane + k * 32];   // L1/L2-resident
        acc = fmaf(xv.x, wv.x, acc);
        acc = fmaf(xv.y, wv.y, acc);
        acc = fmaf(xv.z, wv.z, acc);
        acc = fmaf(xv.w, wv.w, acc);
    }
#pragma unroll
    for (int o = 16; o; o >>= 1) acc += __shfl_xor_sync(0xffffffffu, acc, o);

    if (lane == 0) {
        float xp = acc + *bias;
        float wz = W[D_DIM];
        g_d[row] = fmaf(0.5f, xp, 0.25f * wz);
    }
}

// Phase 2: 64 independent chains (one per batch lane).
//   u_t = tanh( d_t + e * u_{t-1} ),   e = 0.25*wz,  u_0 = -1  (z_0 = 0)
//   z_t = 0.5 + 0.5*u_t   (off the recurrence chain)
// Chain/step = FFMA + MUFU.TANH ~= 21 cyc. 16-deep register prefetch via
// volatile LDG hides L2 latency under the chain.
__global__ __launch_bounds__(64) void scan_kernel(const float* __restrict__ W,
                                                  float* __restrict__ out) {
    const int b = threadIdx.x;                 // 0..63
    const float e = 0.25f * W[D_DIM];
    float u = -1.0f;

    constexpr int CH  = 16;
    constexpr int NCH = T_DIM / CH;
    float buf[2][CH];

#pragma unroll
    for (int i = 0; i < CH; i++) buf[0][i] = ldg_nc(&g_d[i * B_DIM + b]);

    for (int c = 0; c < NCH; c++) {
        const int cur = c & 1;
        if (c + 1 < NCH) {
            const float* ap = g_d + (c + 1) * CH * B_DIM + b;
#pragma unroll
            for (int i = 0; i < CH; i++) buf[cur ^ 1][i] = ldg_nc(ap + i * B_DIM);
        }
        float* __restrict__ op = out + c * CH * B_DIM + b;
#pragma unroll
        for (int i = 0; i < CH; i++) {
            float h = fmaf(u, e, buf[cur][i]);   // ~5 cyc (cross-pipe)
            u = tanh_approx(h);                  // 16 cyc MUFU.TANH
            op[i * B_DIM] = fmaf(u, 0.5f, 0.5f); // off-chain
        }
    }
}

extern "C" void kernel_launch(void* const* d_in, const int* in_sizes, int n_in,
                              void* d_out, int out_size) {
    const float* x    = (const float*)d_in[0];  // (T, B, D) f32
    const float* W    = (const float*)d_in[1];  // (D+1,)    f32
    const float* bias = (const float*)d_in[2];  // ()        f32
    float* out = (float*)d_out;                 // (T, B)    f32

    proj_kernel<<<(T_DIM * B_DIM) / 8, 256>>>(x, W, bias);
    scan_kernel<<<1, 64>>>(W, out);
}